// round 1
// baseline (speedup 1.0000x reference)
#include <cuda_runtime.h>

// Problem constants (fixed by the dataset):
// x: [1, 8192, 3] f32, y: [1, 8192, 3] f32, y_fea: [1, 8192, 16] f32
// out: [1, 8192, 16] f32
// sigmas 0.05/0.1/0.2 -> exp coefficients -200, -50, -12.5 (powers 16/4/1 of e3)
// weights 0.3, 0.3, 0.4

#define N_PTS   8192
#define M_PTS   8192
#define C_FEA   16
#define KSPLIT  32           // M split into 32 chunks of 256
#define TM      (M_PTS / KSPLIT)   // 256 m-points per chunk
#define ROWS    256          // n-rows per block == threads per block

// Static device scratch (no allocations allowed in kernel_launch).
// Partial feature sums and partial row-sums per (sigma, chunk, n).
__device__ float g_pfeat[3][KSPLIT][N_PTS][C_FEA];  // 50.3 MB
__device__ float g_psum [3][KSPLIT][N_PTS];         //  3.1 MB

typedef unsigned long long ull;

__device__ __forceinline__ ull pack2(float a, float b) {
    ull r;
    asm("mov.b64 %0, {%1, %2};" : "=l"(r) : "f"(a), "f"(b));
    return r;
}
__device__ __forceinline__ void fma2(ull& acc, ull a, ull b) {
    // packed f32x2 FMA (Blackwell sm_103a) — 2 fp32 FMAs per instruction
    asm("fma.rn.f32x2 %0, %1, %2, %0;" : "+l"(acc) : "l"(a), "l"(b));
}
__device__ __forceinline__ float2 unpack2(ull v) {
    float2 f;
    asm("mov.b64 {%0, %1}, %2;" : "=f"(f.x), "=f"(f.y) : "l"(v));
    return f;
}

__global__ __launch_bounds__(ROWS) void mgsc_pass1(
    const float* __restrict__ x,
    const float* __restrict__ y,
    const float* __restrict__ yfea)
{
    __shared__ float  sy0[TM], sy1[TM], sy2[TM];
    __shared__ float4 syf4[TM * 4];   // y_fea tile: 256 rows x 16 f32 = 4 float4/row

    const int tid   = threadIdx.x;
    const int nblk  = blockIdx.x;    // 0..31
    const int chunk = blockIdx.y;    // 0..KSPLIT-1
    const int n     = nblk * ROWS + tid;
    const int mbase = chunk * TM;

    // Stage y (SoA) — TM == ROWS so each thread loads one point
    {
        int m = mbase + tid;
        sy0[tid] = y[m * 3 + 0];
        sy1[tid] = y[m * 3 + 1];
        sy2[tid] = y[m * 3 + 2];
    }
    // Stage y_fea as float4 (coalesced)
    {
        const float4* gy4 = reinterpret_cast<const float4*>(yfea + (size_t)mbase * C_FEA);
        #pragma unroll
        for (int i = tid; i < TM * 4; i += ROWS) syf4[i] = gy4[i];
    }
    __syncthreads();

    const float x0 = x[n * 3 + 0];
    const float x1 = x[n * 3 + 1];
    const float x2 = x[n * 3 + 2];

    float s1 = 0.f, s2 = 0.f, s3 = 0.f;   // row-sums for sigma 0.05 / 0.1 / 0.2
    ull A1[8], A2[8], A3[8];              // packed feature accumulators (16 f32 each)
    #pragma unroll
    for (int j = 0; j < 8; ++j) { A1[j] = 0ull; A2[j] = 0ull; A3[j] = 0ull; }

    for (int t = 0; t < TM; ++t) {
        const float d0 = x0 - sy0[t];
        const float d1 = x1 - sy1[t];
        const float d2v = x2 - sy2[t];
        const float dist2 = fmaf(d2v, d2v, fmaf(d1, d1, d0 * d0));

        // e3 = exp(-12.5*d2); e2 = e3^4 = exp(-50*d2); e1 = e3^16 = exp(-200*d2)
        const float e3 = __expf(-12.5f * dist2);
        const float q  = e3 * e3;
        const float e2 = q * q;
        const float r  = e2 * e2;
        const float e1 = r * r;

        s1 += e1; s2 += e2; s3 += e3;

        const ull E1 = pack2(e1, e1);
        const ull E2 = pack2(e2, e2);
        const ull E3 = pack2(e3, e3);

        const ull* yfp = reinterpret_cast<const ull*>(&syf4[t * 4]);
        #pragma unroll
        for (int j = 0; j < 8; ++j) {
            const ull Y = yfp[j];
            fma2(A1[j], E1, Y);
            fma2(A2[j], E2, Y);
            fma2(A3[j], E3, Y);
        }
    }

    // Write partials
    g_psum[0][chunk][n] = s1;
    g_psum[1][chunk][n] = s2;
    g_psum[2][chunk][n] = s3;

    float2* p0 = reinterpret_cast<float2*>(&g_pfeat[0][chunk][n][0]);
    float2* p1 = reinterpret_cast<float2*>(&g_pfeat[1][chunk][n][0]);
    float2* p2 = reinterpret_cast<float2*>(&g_pfeat[2][chunk][n][0]);
    #pragma unroll
    for (int j = 0; j < 8; ++j) {
        p0[j] = unpack2(A1[j]);
        p1[j] = unpack2(A2[j]);
        p2[j] = unpack2(A3[j]);
    }
}

__global__ __launch_bounds__(256) void mgsc_reduce(float* __restrict__ out)
{
    const int tid = threadIdx.x;
    const int c   = tid & 15;
    const int ln  = tid >> 4;
    const int n   = blockIdx.x * 16 + ln;

    float a0 = 0.f, a1 = 0.f, a2 = 0.f;
    float s0 = 0.f, s1 = 0.f, s2 = 0.f;
    #pragma unroll
    for (int k = 0; k < KSPLIT; ++k) {
        a0 += g_pfeat[0][k][n][c];
        a1 += g_pfeat[1][k][n][c];
        a2 += g_pfeat[2][k][n][c];
        s0 += g_psum[0][k][n];
        s1 += g_psum[1][k][n];
        s2 += g_psum[2][k][n];
    }
    out[n * C_FEA + c] = 0.3f * a0 / s0 + 0.3f * a1 / s1 + 0.4f * a2 / s2;
}

extern "C" void kernel_launch(void* const* d_in, const int* in_sizes, int n_in,
                              void* d_out, int out_size)
{
    const float* x    = (const float*)d_in[0];
    const float* y    = (const float*)d_in[1];
    const float* yfea = (const float*)d_in[2];
    float*       out  = (float*)d_out;

    dim3 grid1(N_PTS / ROWS, KSPLIT);   // (32, 32)
    mgsc_pass1<<<grid1, ROWS>>>(x, y, yfea);

    mgsc_reduce<<<N_PTS / 16, 256>>>(out);   // 512 blocks x 256 threads
}

// round 3
// speedup vs baseline: 2.0743x; 2.0743x over previous
#include <cuda_runtime.h>
#include <cstdint>

// x: [8192,3] f32, y: [8192,3] f32, y_fea: [8192,16] f32 -> out [8192,16] f32
// k_sigma: exp(-200 d2)=e3^16, exp(-50 d2)=e3^4, exp(-12.5 d2)=e3; w=0.3/0.3/0.4
// Contraction via legacy mma.sync.m16n8k8 tf32 (compute_103-safe; tcgen05 is NOT
// accepted by this harness's ptxas target). A-fragments generated in registers.

#define N_PTS    8192
#define M_PTS    8192
#define KB_SPLIT 8
#define M_PER_CTA (M_PTS / KB_SPLIT)     // 1024
#define MS       128                     // m-tile staged in SMEM
#define NSTAGE   (M_PER_CTA / MS)        // 8
#define THREADS  256                     // 8 warps x 16 n-rows = 128 n per CTA

typedef unsigned long long ull;

// static scratch (allocations are forbidden)
__device__ float g_U[3][KB_SPLIT][N_PTS][16];   // 12.6 MB
__device__ float g_S[3][KB_SPLIT][N_PTS];       // 0.8 MB

__device__ __forceinline__ ull pack2(float a, float b) {
    ull r; asm("mov.b64 %0, {%1, %2};" : "=l"(r) : "f"(a), "f"(b)); return r;
}
__device__ __forceinline__ float2 unpack2(ull v) {
    float2 f; asm("mov.b64 {%0, %1}, %2;" : "=f"(f.x), "=f"(f.y) : "l"(v)); return f;
}
__device__ __forceinline__ ull add2(ull a, ull b) {
    ull r; asm("add.rn.f32x2 %0, %1, %2;" : "=l"(r) : "l"(a), "l"(b)); return r;
}
__device__ __forceinline__ ull mul2(ull a, ull b) {
    ull r; asm("mul.rn.f32x2 %0, %1, %2;" : "=l"(r) : "l"(a), "l"(b)); return r;
}
__device__ __forceinline__ ull fma2v(ull a, ull b, ull c) {
    ull r; asm("fma.rn.f32x2 %0, %1, %2, %3;" : "=l"(r) : "l"(a), "l"(b), "l"(c)); return r;
}
__device__ __forceinline__ float ex2f(float x) {
    float r; asm("ex2.approx.f32 %0, %1;" : "=f"(r) : "f"(x)); return r;
}
// round-to-nearest tf32 (result is a valid f32 bit pattern with low 13 bits 0)
__device__ __forceinline__ uint32_t tf32r(float f) {
    uint32_t u; asm("cvt.rna.tf32.f32 %0, %1;" : "=r"(u) : "f"(f)); return u;
}

__device__ __forceinline__ void mma_tf32(float& d0, float& d1, float& d2, float& d3,
                                         uint32_t a0, uint32_t a1, uint32_t a2, uint32_t a3,
                                         uint32_t b0, uint32_t b1) {
    asm volatile(
        "mma.sync.aligned.m16n8k8.row.col.f32.tf32.tf32.f32 "
        "{%0,%1,%2,%3}, {%4,%5,%6,%7}, {%8,%9}, {%0,%1,%2,%3};"
        : "+f"(d0), "+f"(d1), "+f"(d2), "+f"(d3)
        : "r"(a0), "r"(a1), "r"(a2), "r"(a3), "r"(b0), "r"(b1));
}

__global__ __launch_bounds__(THREADS) void mgsc_pass1(
    const float* __restrict__ x,
    const float* __restrict__ y,
    const float* __restrict__ yfea)
{
    __shared__ float ys[3][MS];          // negated y tile (SoA)
    __shared__ float yfs[MS * 16];       // y_fea tile, tf32-rounded

    const int tid  = threadIdx.x;
    const int warp = tid >> 5;
    const int lane = tid & 31;
    const int g    = lane >> 2;          // fragment group row
    const int t    = lane & 3;           // fragment k index
    const int nb   = blockIdx.x * 128 + warp * 16;
    const int mstart = blockIdx.y * M_PER_CTA;

    // x for this thread's two fragment rows, packed (row g, row g+8)
    const int rlo = nb + g, rhi = nb + g + 8;
    const ull X0 = pack2(x[rlo*3+0], x[rhi*3+0]);
    const ull X1 = pack2(x[rlo*3+1], x[rhi*3+1]);
    const ull X2 = pack2(x[rlo*3+2], x[rhi*3+2]);
    const float cexp = -12.5f * 1.44269504088896340736f;
    const ull CC = pack2(cexp, cexp);

    // accumulators: D[sig][frag][4], row-sums (lo=row g, hi=row g+8)
    float D[3][2][4];
    float slo[3], shi[3];
    #pragma unroll
    for (int s = 0; s < 3; s++) {
        slo[s] = 0.f; shi[s] = 0.f;
        #pragma unroll
        for (int f = 0; f < 2; f++)
            #pragma unroll
            for (int q = 0; q < 4; q++) D[s][f][q] = 0.f;
    }

    for (int st = 0; st < NSTAGE; st++) {
        if (st) __syncthreads();
        // stage y (negated) and y_fea (tf32-rounded)
        {
            if (tid < MS) {
                int m = mstart + st * MS + tid;
                ys[0][tid] = -y[m*3+0];
                ys[1][tid] = -y[m*3+1];
                ys[2][tid] = -y[m*3+2];
            }
            const float4* src = reinterpret_cast<const float4*>(
                yfea + (size_t)(mstart + st * MS) * 16);
            float4* dst = reinterpret_cast<float4*>(yfs);
            #pragma unroll
            for (int q = 0; q < 2; q++) {
                float4 v = src[tid + q * 256];
                v.x = __uint_as_float(tf32r(v.x));
                v.y = __uint_as_float(tf32r(v.y));
                v.z = __uint_as_float(tf32r(v.z));
                v.w = __uint_as_float(tf32r(v.w));
                dst[tid + q * 256] = v;
            }
        }
        __syncthreads();

        #pragma unroll 4
        for (int c8 = 0; c8 < MS / 8; c8++) {
            const int mloc = c8 * 8;
            // chain A: col t ;  chain B: col t+4   (each packs rows g, g+8)
            const float ya0 = ys[0][mloc+t],   ya1 = ys[1][mloc+t],   ya2 = ys[2][mloc+t];
            const float yb0 = ys[0][mloc+t+4], yb1 = ys[1][mloc+t+4], yb2 = ys[2][mloc+t+4];

            ull dA = add2(X0, pack2(ya0, ya0));
            ull sA = mul2(dA, dA);
            dA = add2(X1, pack2(ya1, ya1)); sA = fma2v(dA, dA, sA);
            dA = add2(X2, pack2(ya2, ya2)); sA = fma2v(dA, dA, sA);
            sA = mul2(sA, CC);
            float2 fA = unpack2(sA);

            ull dB = add2(X0, pack2(yb0, yb0));
            ull sB = mul2(dB, dB);
            dB = add2(X1, pack2(yb1, yb1)); sB = fma2v(dB, dB, sB);
            dB = add2(X2, pack2(yb2, yb2)); sB = fma2v(dB, dB, sB);
            sB = mul2(sB, CC);
            float2 fB = unpack2(sB);

            float e3v[4];
            e3v[0] = ex2f(fA.x);   // (row g,   col t)
            e3v[1] = ex2f(fA.y);   // (row g+8, col t)
            e3v[2] = ex2f(fB.x);   // (row g,   col t+4)
            e3v[3] = ex2f(fB.y);   // (row g+8, col t+4)

            uint32_t A1[4], A2[4], A3[4];
            #pragma unroll
            for (int j = 0; j < 4; j++) {
                float e3 = e3v[j];
                float q  = e3 * e3;
                float e2 = q * q;
                float r  = e2 * e2;
                float e1 = r * r;
                A3[j] = tf32r(e3);
                A2[j] = tf32r(e2);
                A1[j] = tf32r(e1);
            }
            // row-sums from the SAME tf32-rounded values (num/denom consistent)
            slo[0] += __uint_as_float(A1[0]) + __uint_as_float(A1[2]);
            shi[0] += __uint_as_float(A1[1]) + __uint_as_float(A1[3]);
            slo[1] += __uint_as_float(A2[0]) + __uint_as_float(A2[2]);
            shi[1] += __uint_as_float(A2[1]) + __uint_as_float(A2[3]);
            slo[2] += __uint_as_float(A3[0]) + __uint_as_float(A3[2]);
            shi[2] += __uint_as_float(A3[1]) + __uint_as_float(A3[3]);

            // B fragments: b0 = yfea[m=t][feat], b1 = yfea[m=t+4][feat]
            const float* bp0 = yfs + (mloc + t) * 16;
            const float* bp1 = yfs + (mloc + t + 4) * 16;
            const uint32_t b0lo = __float_as_uint(bp0[g]);
            const uint32_t b1lo = __float_as_uint(bp1[g]);
            const uint32_t b0hi = __float_as_uint(bp0[g + 8]);
            const uint32_t b1hi = __float_as_uint(bp1[g + 8]);

            mma_tf32(D[0][0][0], D[0][0][1], D[0][0][2], D[0][0][3],
                     A1[0], A1[1], A1[2], A1[3], b0lo, b1lo);
            mma_tf32(D[0][1][0], D[0][1][1], D[0][1][2], D[0][1][3],
                     A1[0], A1[1], A1[2], A1[3], b0hi, b1hi);
            mma_tf32(D[1][0][0], D[1][0][1], D[1][0][2], D[1][0][3],
                     A2[0], A2[1], A2[2], A2[3], b0lo, b1lo);
            mma_tf32(D[1][1][0], D[1][1][1], D[1][1][2], D[1][1][3],
                     A2[0], A2[1], A2[2], A2[3], b0hi, b1hi);
            mma_tf32(D[2][0][0], D[2][0][1], D[2][0][2], D[2][0][3],
                     A3[0], A3[1], A3[2], A3[3], b0lo, b1lo);
            mma_tf32(D[2][1][0], D[2][1][1], D[2][1][2], D[2][1][3],
                     A3[0], A3[1], A3[2], A3[3], b0hi, b1hi);
        }
    }

    // reduce row-sums across the 4 lanes sharing a group (cols t=0..3)
    const int kb = blockIdx.y;
    #pragma unroll
    for (int s = 0; s < 3; s++) {
        float a = slo[s], b = shi[s];
        a += __shfl_xor_sync(0xffffffffu, a, 1);
        a += __shfl_xor_sync(0xffffffffu, a, 2);
        b += __shfl_xor_sync(0xffffffffu, b, 1);
        b += __shfl_xor_sync(0xffffffffu, b, 2);
        if (t == 0) {
            g_S[s][kb][rlo] = a;
            g_S[s][kb][rhi] = b;
        }
    }
    // D fragment -> g_U : d0/d1 = (row g, cols 2t,2t+1), d2/d3 = (row g+8, ...)
    #pragma unroll
    for (int s = 0; s < 3; s++)
        #pragma unroll
        for (int f = 0; f < 2; f++) {
            const int c = f * 8 + 2 * t;
            *reinterpret_cast<float2*>(&g_U[s][kb][rlo][c]) =
                make_float2(D[s][f][0], D[s][f][1]);
            *reinterpret_cast<float2*>(&g_U[s][kb][rhi][c]) =
                make_float2(D[s][f][2], D[s][f][3]);
        }
}

__global__ __launch_bounds__(256) void mgsc_reduce(float* __restrict__ out)
{
    const int tid = threadIdx.x;
    const int c = tid & 15;
    const int n = blockIdx.x * 16 + (tid >> 4);
    const float w[3] = {0.3f, 0.3f, 0.4f};
    float acc = 0.f;
    #pragma unroll
    for (int s = 0; s < 3; s++) {
        float u = 0.f, sm = 0.f;
        #pragma unroll
        for (int k = 0; k < KB_SPLIT; k++) {
            u  += g_U[s][k][n][c];
            sm += g_S[s][k][n];
        }
        acc += w[s] * u / sm;
    }
    out[n * 16 + c] = acc;
}

extern "C" void kernel_launch(void* const* d_in, const int* in_sizes, int n_in,
                              void* d_out, int out_size)
{
    const float* x    = (const float*)d_in[0];
    const float* y    = (const float*)d_in[1];
    const float* yfea = (const float*)d_in[2];
    float*       out  = (float*)d_out;

    dim3 grid(N_PTS / 128, KB_SPLIT);        // (64, 8) = 512 CTAs
    mgsc_pass1<<<grid, THREADS>>>(x, y, yfea);
    mgsc_reduce<<<N_PTS / 16, 256>>>(out);
}

// round 4
// speedup vs baseline: 2.3855x; 1.1500x over previous
#include <cuda_runtime.h>
#include <cstdint>

// x: [8192,3] f32, y: [8192,3] f32, y_fea: [8192,16] f32 -> out [8192,16] f32
// k_sigma: exp(-200 d2)=e3^16, exp(-50 d2)=e3^4, exp(-12.5 d2)=e3; w=0.3/0.3/0.4
// Expanded form: Cexp*d2 = Cexp|x|^2 + Cexp|y|^2 - 2Cexp x.y  (Cexp = -12.5*log2 e)
// Contraction via mma.sync.m16n8k8 tf32 (compute_103-safe), A-fragments in regs.

#define N_PTS    8192
#define M_PTS    8192
#define KB_SPLIT 16
#define M_PER_CTA (M_PTS / KB_SPLIT)     // 512
#define MS       128                     // m-tile staged in SMEM
#define NSTAGE   (M_PER_CTA / MS)        // 4
#define THREADS  256                     // 8 warps x 16 n-rows = 128 n per CTA

typedef unsigned long long ull;

// static scratch (allocations are forbidden)
__device__ float g_U[3][KB_SPLIT][N_PTS][16];   // 25.2 MB (L2-resident)
__device__ float g_S[3][KB_SPLIT][N_PTS];       //  1.6 MB

__device__ __forceinline__ ull pack2(float a, float b) {
    ull r; asm("mov.b64 %0, {%1, %2};" : "=l"(r) : "f"(a), "f"(b)); return r;
}
__device__ __forceinline__ float2 unpack2(ull v) {
    float2 f; asm("mov.b64 {%0, %1}, %2;" : "=f"(f.x), "=f"(f.y) : "l"(v)); return f;
}
__device__ __forceinline__ ull add2(ull a, ull b) {
    ull r; asm("add.rn.f32x2 %0, %1, %2;" : "=l"(r) : "l"(a), "l"(b)); return r;
}
__device__ __forceinline__ ull mul2(ull a, ull b) {
    ull r; asm("mul.rn.f32x2 %0, %1, %2;" : "=l"(r) : "l"(a), "l"(b)); return r;
}
__device__ __forceinline__ ull fma2v(ull a, ull b, ull c) {
    ull r; asm("fma.rn.f32x2 %0, %1, %2, %3;" : "=l"(r) : "l"(a), "l"(b), "l"(c)); return r;
}
__device__ __forceinline__ float ex2f(float x) {
    float r; asm("ex2.approx.f32 %0, %1;" : "=f"(r) : "f"(x)); return r;
}
__device__ __forceinline__ uint32_t tf32r(float f) {
    uint32_t u; asm("cvt.rna.tf32.f32 %0, %1;" : "=r"(u) : "f"(f)); return u;
}

__device__ __forceinline__ void mma_tf32(float& d0, float& d1, float& d2, float& d3,
                                         uint32_t a0, uint32_t a1, uint32_t a2, uint32_t a3,
                                         uint32_t b0, uint32_t b1) {
    asm volatile(
        "mma.sync.aligned.m16n8k8.row.col.f32.tf32.tf32.f32 "
        "{%0,%1,%2,%3}, {%4,%5,%6,%7}, {%8,%9}, {%0,%1,%2,%3};"
        : "+f"(d0), "+f"(d1), "+f"(d2), "+f"(d3)
        : "r"(a0), "r"(a1), "r"(a2), "r"(a3), "r"(b0), "r"(b1));
}

__global__ __launch_bounds__(THREADS) void mgsc_pass1(
    const float* __restrict__ x,
    const float* __restrict__ y,
    const float* __restrict__ yfea)
{
    // y staged as interleaved (m, m+4) pairs: ysw[pair][comp 0..3] where
    // comps = { y'0, y'1, y'2, b }, y' = -2*Cexp*y, b = Cexp*|y|^2.
    __shared__ __align__(16) ull ysw[MS / 2][4];    // 2 KB
    __shared__ float yfs[MS * 16];                  // 8 KB, tf32-rounded y_fea

    const int tid  = threadIdx.x;
    const int warp = tid >> 5;
    const int lane = tid & 31;
    const int g    = lane >> 2;          // fragment group row (0..7)
    const int t    = lane & 3;           // fragment k index (0..3)
    const int nb   = blockIdx.x * 128 + warp * 16;
    const int mstart = blockIdx.y * M_PER_CTA;
    const int kb   = blockIdx.y;

    const float Cexp = -12.5f * 1.44269504088896340736f;

    // per-thread constants for the two fragment rows (broadcast-packed once)
    const int rlo = nb + g, rhi = nb + g + 8;
    const float xl0 = x[rlo*3+0], xl1 = x[rlo*3+1], xl2 = x[rlo*3+2];
    const float xh0 = x[rhi*3+0], xh1 = x[rhi*3+1], xh2 = x[rhi*3+2];
    const float al = Cexp * (xl0*xl0 + xl1*xl1 + xl2*xl2);
    const float ah = Cexp * (xh0*xh0 + xh1*xh1 + xh2*xh2);
    const ull X0l = pack2(xl0, xl0), X1l = pack2(xl1, xl1), X2l = pack2(xl2, xl2);
    const ull X0h = pack2(xh0, xh0), X1h = pack2(xh1, xh1), X2h = pack2(xh2, xh2);
    const ull APl = pack2(al, al),   APh = pack2(ah, ah);

    float D[3][2][4];
    ull S1l = 0, S2l = 0, S3l = 0, S1h = 0, S2h = 0, S3h = 0;
    #pragma unroll
    for (int s = 0; s < 3; s++)
        #pragma unroll
        for (int f = 0; f < 2; f++)
            #pragma unroll
            for (int q = 0; q < 4; q++) D[s][f][q] = 0.f;

    for (int st = 0; st < NSTAGE; st++) {
        if (st) __syncthreads();
        // ---- stage y (transformed) and y_fea (tf32-rounded) ----
        if (tid < MS) {
            const int m = mstart + st * MS + tid;
            const float y0 = y[m*3+0], y1 = y[m*3+1], y2 = y[m*3+2];
            const float b  = Cexp * (y0*y0 + y1*y1 + y2*y2);
            const float sc = -2.0f * Cexp;
            const int p = (tid >> 3) * 4 + (tid & 3);
            const int h = (tid >> 2) & 1;
            float* w = (float*)&ysw[p][0];
            w[0*2+h] = sc * y0;
            w[1*2+h] = sc * y1;
            w[2*2+h] = sc * y2;
            w[3*2+h] = b;
        }
        {
            const float4* src = reinterpret_cast<const float4*>(
                yfea + (size_t)(mstart + st * MS) * 16);
            float4* dst = reinterpret_cast<float4*>(yfs);
            #pragma unroll
            for (int q = 0; q < 2; q++) {
                float4 v = src[tid + q * 256];
                v.x = __uint_as_float(tf32r(v.x));
                v.y = __uint_as_float(tf32r(v.y));
                v.z = __uint_as_float(tf32r(v.z));
                v.w = __uint_as_float(tf32r(v.w));
                dst[tid + q * 256] = v;
            }
        }
        __syncthreads();

        #pragma unroll 4
        for (int c8 = 0; c8 < MS / 8; c8++) {
            const int mloc = c8 * 8;
            // packed y operands for cols (t, t+4): 2x LDS.128
            const ulonglong2 q0 = *reinterpret_cast<const ulonglong2*>(&ysw[c8*4 + t][0]);
            const ulonglong2 q1 = *reinterpret_cast<const ulonglong2*>(&ysw[c8*4 + t][2]);
            const ull y0p = q0.x, y1p = q0.y, y2p = q1.x, bp = q1.y;

            // arg = a + b + x.y'  (packed over cols t, t+4), rows g and g+8
            ull argl = add2(APl, bp);
            argl = fma2v(X0l, y0p, argl);
            argl = fma2v(X1l, y1p, argl);
            argl = fma2v(X2l, y2p, argl);
            ull argh = add2(APh, bp);
            argh = fma2v(X0h, y0p, argh);
            argh = fma2v(X1h, y1p, argh);
            argh = fma2v(X2h, y2p, argh);

            const float2 fl = unpack2(argl), fh = unpack2(argh);
            const ull e3l = pack2(ex2f(fl.x), ex2f(fl.y));
            const ull e3h = pack2(ex2f(fh.x), ex2f(fh.y));

            // packed power ladder: e2 = e3^4, e1 = e3^16
            const ull ql  = mul2(e3l, e3l), qh  = mul2(e3h, e3h);
            const ull e2l = mul2(ql, ql),   e2h = mul2(qh, qh);
            const ull rl  = mul2(e2l, e2l), rh  = mul2(e2h, e2h);
            const ull e1l = mul2(rl, rl),   e1h = mul2(rh, rh);

            // packed row-sums (unrounded f32; numerator uses tf32-rounded —
            // consistent enough: ladder/rounding err ~1e-4 << 1e-3)
            S3l = add2(S3l, e3l); S3h = add2(S3h, e3h);
            S2l = add2(S2l, e2l); S2h = add2(S2h, e2h);
            S1l = add2(S1l, e1l); S1h = add2(S1h, e1h);

            // tf32 fragments: a0=(g,t) a1=(g+8,t) a2=(g,t+4) a3=(g+8,t+4)
            const float2 e1lf = unpack2(e1l), e1hf = unpack2(e1h);
            const float2 e2lf = unpack2(e2l), e2hf = unpack2(e2h);
            const float2 e3lf = unpack2(e3l), e3hf = unpack2(e3h);
            uint32_t A1[4], A2[4], A3[4];
            A1[0] = tf32r(e1lf.x); A1[2] = tf32r(e1lf.y);
            A1[1] = tf32r(e1hf.x); A1[3] = tf32r(e1hf.y);
            A2[0] = tf32r(e2lf.x); A2[2] = tf32r(e2lf.y);
            A2[1] = tf32r(e2hf.x); A2[3] = tf32r(e2hf.y);
            A3[0] = tf32r(e3lf.x); A3[2] = tf32r(e3lf.y);
            A3[1] = tf32r(e3hf.x); A3[3] = tf32r(e3hf.y);

            const float* bp0 = yfs + (mloc + t) * 16;
            const float* bp1 = yfs + (mloc + t + 4) * 16;
            const uint32_t b0lo = __float_as_uint(bp0[g]);
            const uint32_t b1lo = __float_as_uint(bp1[g]);
            const uint32_t b0hi = __float_as_uint(bp0[g + 8]);
            const uint32_t b1hi = __float_as_uint(bp1[g + 8]);

            mma_tf32(D[0][0][0], D[0][0][1], D[0][0][2], D[0][0][3],
                     A1[0], A1[1], A1[2], A1[3], b0lo, b1lo);
            mma_tf32(D[0][1][0], D[0][1][1], D[0][1][2], D[0][1][3],
                     A1[0], A1[1], A1[2], A1[3], b0hi, b1hi);
            mma_tf32(D[1][0][0], D[1][0][1], D[1][0][2], D[1][0][3],
                     A2[0], A2[1], A2[2], A2[3], b0lo, b1lo);
            mma_tf32(D[1][1][0], D[1][1][1], D[1][1][2], D[1][1][3],
                     A2[0], A2[1], A2[2], A2[3], b0hi, b1hi);
            mma_tf32(D[2][0][0], D[2][0][1], D[2][0][2], D[2][0][3],
                     A3[0], A3[1], A3[2], A3[3], b0lo, b1lo);
            mma_tf32(D[2][1][0], D[2][1][1], D[2][1][2], D[2][1][3],
                     A3[0], A3[1], A3[2], A3[3], b0hi, b1hi);
        }
    }

    // row-sums: horizontal add of packed halves, then reduce over the 4 t-lanes
    {
        float sl[3], sh[3];
        float2 v;
        v = unpack2(S1l); sl[0] = v.x + v.y;  v = unpack2(S1h); sh[0] = v.x + v.y;
        v = unpack2(S2l); sl[1] = v.x + v.y;  v = unpack2(S2h); sh[1] = v.x + v.y;
        v = unpack2(S3l); sl[2] = v.x + v.y;  v = unpack2(S3h); sh[2] = v.x + v.y;
        #pragma unroll
        for (int s = 0; s < 3; s++) {
            float a = sl[s], b = sh[s];
            a += __shfl_xor_sync(0xffffffffu, a, 1);
            a += __shfl_xor_sync(0xffffffffu, a, 2);
            b += __shfl_xor_sync(0xffffffffu, b, 1);
            b += __shfl_xor_sync(0xffffffffu, b, 2);
            if (t == 0) {
                g_S[s][kb][rlo] = a;
                g_S[s][kb][rhi] = b;
            }
        }
    }
    // D fragment -> g_U : d0/d1 = (row g, cols 2t,2t+1), d2/d3 = (row g+8, ...)
    #pragma unroll
    for (int s = 0; s < 3; s++)
        #pragma unroll
        for (int f = 0; f < 2; f++) {
            const int c = f * 8 + 2 * t;
            *reinterpret_cast<float2*>(&g_U[s][kb][rlo][c]) =
                make_float2(D[s][f][0], D[s][f][1]);
            *reinterpret_cast<float2*>(&g_U[s][kb][rhi][c]) =
                make_float2(D[s][f][2], D[s][f][3]);
        }
}

__global__ __launch_bounds__(256) void mgsc_reduce(float* __restrict__ out)
{
    const int idx = blockIdx.x * 256 + threadIdx.x;   // 32768 threads
    const int n  = idx >> 2;
    const int cq = (idx & 3) * 4;

    float4 u[3];
    float  sm[3];
    #pragma unroll
    for (int s = 0; s < 3; s++) { u[s] = make_float4(0,0,0,0); sm[s] = 0.f; }

    #pragma unroll
    for (int k = 0; k < KB_SPLIT; k++)
        #pragma unroll
        for (int s = 0; s < 3; s++) {
            const float4 v = *reinterpret_cast<const float4*>(&g_U[s][k][n][cq]);
            u[s].x += v.x; u[s].y += v.y; u[s].z += v.z; u[s].w += v.w;
            sm[s] += g_S[s][k][n];
        }

    const float w[3] = {0.3f, 0.3f, 0.4f};
    float4 acc = make_float4(0,0,0,0);
    #pragma unroll
    for (int s = 0; s < 3; s++) {
        const float iv = w[s] / sm[s];
        acc.x += u[s].x * iv; acc.y += u[s].y * iv;
        acc.z += u[s].z * iv; acc.w += u[s].w * iv;
    }
    *reinterpret_cast<float4*>(&out[n * 16 + cq]) = acc;
}

extern "C" void kernel_launch(void* const* d_in, const int* in_sizes, int n_in,
                              void* d_out, int out_size)
{
    const float* x    = (const float*)d_in[0];
    const float* y    = (const float*)d_in[1];
    const float* yfea = (const float*)d_in[2];
    float*       out  = (float*)d_out;

    dim3 grid(N_PTS / 128, KB_SPLIT);        // (64, 16) = 1024 CTAs
    mgsc_pass1<<<grid, THREADS>>>(x, y, yfea);
    mgsc_reduce<<<(N_PTS * 16 / 4) / 256, 256>>>(out);   // 128 blocks
}

// round 5
// speedup vs baseline: 2.6377x; 1.1057x over previous
#include <cuda_runtime.h>
#include <cstdint>

// x: [8192,3] f32, y: [8192,3] f32, y_fea: [8192,16] f32 -> out [8192,16] f32
// k_sigma: exp(-200 d2)=e3^16, exp(-50 d2)=e3^4, exp(-12.5 d2)=e3; w=0.3/0.3/0.4
// Expanded form: Cexp*d2 = Cexp|x|^2 + Cexp|y|^2 - 2Cexp x.y  (Cexp = -12.5*log2 e)
// Contraction via mma.sync.m16n8k8 tf32. A operands fed as raw f32 (HW tf32
// truncation); row-sums produced by a ones-column MMA so numerator and
// denominator see IDENTICAL truncation (bias cancels in the ratio).

#define N_PTS    8192
#define M_PTS    8192
#define KB_SPLIT 16
#define M_PER_CTA (M_PTS / KB_SPLIT)     // 512
#define MS       128                     // m-tile staged in SMEM
#define NSTAGE   (M_PER_CTA / MS)        // 4
#define THREADS  256                     // 8 warps x 16 n-rows = 128 n per CTA

typedef unsigned long long ull;

// static scratch (allocations are forbidden)
__device__ float g_U[3][KB_SPLIT][N_PTS][16];   // 25.2 MB (L2-resident)
__device__ float g_S[3][KB_SPLIT][N_PTS];       //  1.6 MB

__device__ __forceinline__ ull pack2(float a, float b) {
    ull r; asm("mov.b64 %0, {%1, %2};" : "=l"(r) : "f"(a), "f"(b)); return r;
}
__device__ __forceinline__ float2 unpack2(ull v) {
    float2 f; asm("mov.b64 {%0, %1}, %2;" : "=f"(f.x), "=f"(f.y) : "l"(v)); return f;
}
__device__ __forceinline__ ull add2(ull a, ull b) {
    ull r; asm("add.rn.f32x2 %0, %1, %2;" : "=l"(r) : "l"(a), "l"(b)); return r;
}
__device__ __forceinline__ ull mul2(ull a, ull b) {
    ull r; asm("mul.rn.f32x2 %0, %1, %2;" : "=l"(r) : "l"(a), "l"(b)); return r;
}
__device__ __forceinline__ ull fma2v(ull a, ull b, ull c) {
    ull r; asm("fma.rn.f32x2 %0, %1, %2, %3;" : "=l"(r) : "l"(a), "l"(b), "l"(c)); return r;
}
__device__ __forceinline__ float ex2f(float x) {
    float r; asm("ex2.approx.f32 %0, %1;" : "=f"(r) : "f"(x)); return r;
}
__device__ __forceinline__ uint32_t tf32r(float f) {
    uint32_t u; asm("cvt.rna.tf32.f32 %0, %1;" : "=r"(u) : "f"(f)); return u;
}

__device__ __forceinline__ void mma_tf32(float& d0, float& d1, float& d2, float& d3,
                                         float a0, float a1, float a2, float a3,
                                         uint32_t b0, uint32_t b1) {
    asm volatile(
        "mma.sync.aligned.m16n8k8.row.col.f32.tf32.tf32.f32 "
        "{%0,%1,%2,%3}, {%4,%5,%6,%7}, {%8,%9}, {%0,%1,%2,%3};"
        : "+f"(d0), "+f"(d1), "+f"(d2), "+f"(d3)
        : "r"(__float_as_uint(a0)), "r"(__float_as_uint(a1)),
          "r"(__float_as_uint(a2)), "r"(__float_as_uint(a3)),
          "r"(b0), "r"(b1));
}

__global__ __launch_bounds__(THREADS) void mgsc_pass1(
    const float* __restrict__ x,
    const float* __restrict__ y,
    const float* __restrict__ yfea)
{
    // y staged as interleaved (m, m+4) pairs: ysw[pair][comp 0..3] where
    // comps = { y'0, y'1, y'2, b }, y' = -2*Cexp*y, b = Cexp*|y|^2.
    __shared__ __align__(16) ull ysw[MS / 2][4];    // 2 KB
    __shared__ float yfs[MS * 16];                  // 8 KB, tf32-rounded y_fea

    const int tid  = threadIdx.x;
    const int warp = tid >> 5;
    const int lane = tid & 31;
    const int g    = lane >> 2;          // fragment group row (0..7)
    const int t    = lane & 3;           // fragment k index (0..3)
    const int nb   = blockIdx.x * 128 + warp * 16;
    const int mstart = blockIdx.y * M_PER_CTA;
    const int kb   = blockIdx.y;

    const float Cexp = -12.5f * 1.44269504088896340736f;

    // per-thread constants for the two fragment rows (broadcast-packed once)
    const int rlo = nb + g, rhi = nb + g + 8;
    const float xl0 = x[rlo*3+0], xl1 = x[rlo*3+1], xl2 = x[rlo*3+2];
    const float xh0 = x[rhi*3+0], xh1 = x[rhi*3+1], xh2 = x[rhi*3+2];
    const float al = Cexp * (xl0*xl0 + xl1*xl1 + xl2*xl2);
    const float ah = Cexp * (xh0*xh0 + xh1*xh1 + xh2*xh2);
    const ull X0l = pack2(xl0, xl0), X1l = pack2(xl1, xl1), X2l = pack2(xl2, xl2);
    const ull X0h = pack2(xh0, xh0), X1h = pack2(xh1, xh1), X2h = pack2(xh2, xh2);
    const ull APl = pack2(al, al),   APh = pack2(ah, ah);

    // ones-column B fragment (col 0 of the 3rd fragment = global col 16)
    const uint32_t bones = (g == 0) ? 0x3f800000u : 0u;

    // D[sig][frag 0..2][4]; frag 2 = ones-column (row-sums live in d0/d2)
    float D[3][3][4];
    #pragma unroll
    for (int s = 0; s < 3; s++)
        #pragma unroll
        for (int f = 0; f < 3; f++)
            #pragma unroll
            for (int q = 0; q < 4; q++) D[s][f][q] = 0.f;

    for (int st = 0; st < NSTAGE; st++) {
        if (st) __syncthreads();
        // ---- stage y (transformed) and y_fea (tf32-rounded) ----
        if (tid < MS) {
            const int m = mstart + st * MS + tid;
            const float y0 = y[m*3+0], y1 = y[m*3+1], y2 = y[m*3+2];
            const float b  = Cexp * (y0*y0 + y1*y1 + y2*y2);
            const float sc = -2.0f * Cexp;
            const int p = (tid >> 3) * 4 + (tid & 3);
            const int h = (tid >> 2) & 1;
            float* w = (float*)&ysw[p][0];
            w[0*2+h] = sc * y0;
            w[1*2+h] = sc * y1;
            w[2*2+h] = sc * y2;
            w[3*2+h] = b;
        }
        {
            const float4* src = reinterpret_cast<const float4*>(
                yfea + (size_t)(mstart + st * MS) * 16);
            float4* dst = reinterpret_cast<float4*>(yfs);
            #pragma unroll
            for (int q = 0; q < 2; q++) {
                float4 v = src[tid + q * 256];
                v.x = __uint_as_float(tf32r(v.x));
                v.y = __uint_as_float(tf32r(v.y));
                v.z = __uint_as_float(tf32r(v.z));
                v.w = __uint_as_float(tf32r(v.w));
                dst[tid + q * 256] = v;
            }
        }
        __syncthreads();

        #pragma unroll 4
        for (int c8 = 0; c8 < MS / 8; c8++) {
            const int mloc = c8 * 8;
            // packed y operands for cols (t, t+4): 2x LDS.128
            const ulonglong2 q0 = *reinterpret_cast<const ulonglong2*>(&ysw[c8*4 + t][0]);
            const ulonglong2 q1 = *reinterpret_cast<const ulonglong2*>(&ysw[c8*4 + t][2]);
            const ull y0p = q0.x, y1p = q0.y, y2p = q1.x, bp = q1.y;

            // arg = a + b + x.y'  (packed over cols t, t+4), rows g and g+8
            ull argl = add2(APl, bp);
            argl = fma2v(X0l, y0p, argl);
            argl = fma2v(X1l, y1p, argl);
            argl = fma2v(X2l, y2p, argl);
            ull argh = add2(APh, bp);
            argh = fma2v(X0h, y0p, argh);
            argh = fma2v(X1h, y1p, argh);
            argh = fma2v(X2h, y2p, argh);

            const float2 fl = unpack2(argl), fh = unpack2(argh);
            const ull e3l = pack2(ex2f(fl.x), ex2f(fl.y));
            const ull e3h = pack2(ex2f(fh.x), ex2f(fh.y));

            // packed power ladder: e2 = e3^4, e1 = e3^16
            const ull ql  = mul2(e3l, e3l), qh  = mul2(e3h, e3h);
            const ull e2l = mul2(ql, ql),   e2h = mul2(qh, qh);
            const ull rl  = mul2(e2l, e2l), rh  = mul2(e2h, e2h);
            const ull e1l = mul2(rl, rl),   e1h = mul2(rh, rh);

            // A fragments (raw f32 -> HW tf32 truncation, same bits for num & denom)
            // a0=(g,t) a1=(g+8,t) a2=(g,t+4) a3=(g+8,t+4)
            const float2 e1lf = unpack2(e1l), e1hf = unpack2(e1h);
            const float2 e2lf = unpack2(e2l), e2hf = unpack2(e2h);
            const float2 e3lf = unpack2(e3l), e3hf = unpack2(e3h);

            const float* bp0 = yfs + (mloc + t) * 16;
            const float* bp1 = yfs + (mloc + t + 4) * 16;
            const uint32_t b0lo = __float_as_uint(bp0[g]);
            const uint32_t b1lo = __float_as_uint(bp1[g]);
            const uint32_t b0hi = __float_as_uint(bp0[g + 8]);
            const uint32_t b1hi = __float_as_uint(bp1[g + 8]);

            mma_tf32(D[0][0][0], D[0][0][1], D[0][0][2], D[0][0][3],
                     e1lf.x, e1hf.x, e1lf.y, e1hf.y, b0lo, b1lo);
            mma_tf32(D[0][1][0], D[0][1][1], D[0][1][2], D[0][1][3],
                     e1lf.x, e1hf.x, e1lf.y, e1hf.y, b0hi, b1hi);
            mma_tf32(D[0][2][0], D[0][2][1], D[0][2][2], D[0][2][3],
                     e1lf.x, e1hf.x, e1lf.y, e1hf.y, bones, bones);
            mma_tf32(D[1][0][0], D[1][0][1], D[1][0][2], D[1][0][3],
                     e2lf.x, e2hf.x, e2lf.y, e2hf.y, b0lo, b1lo);
            mma_tf32(D[1][1][0], D[1][1][1], D[1][1][2], D[1][1][3],
                     e2lf.x, e2hf.x, e2lf.y, e2hf.y, b0hi, b1hi);
            mma_tf32(D[1][2][0], D[1][2][1], D[1][2][2], D[1][2][3],
                     e2lf.x, e2hf.x, e2lf.y, e2hf.y, bones, bones);
            mma_tf32(D[2][0][0], D[2][0][1], D[2][0][2], D[2][0][3],
                     e3lf.x, e3hf.x, e3lf.y, e3hf.y, b0lo, b1lo);
            mma_tf32(D[2][1][0], D[2][1][1], D[2][1][2], D[2][1][3],
                     e3lf.x, e3hf.x, e3lf.y, e3hf.y, b0hi, b1hi);
            mma_tf32(D[2][2][0], D[2][2][1], D[2][2][2], D[2][2][3],
                     e3lf.x, e3hf.x, e3lf.y, e3hf.y, bones, bones);
        }
    }

    // row-sums come straight out of the ones-column fragment:
    // D[s][2]: d0 = (row g, col 0), d2 = (row g+8, col 0) -> held by t==0... col = 2t
    if (t == 0) {
        #pragma unroll
        for (int s = 0; s < 3; s++) {
            g_S[s][kb][rlo] = D[s][2][0];
            g_S[s][kb][rhi] = D[s][2][2];
        }
    }
    // D fragment -> g_U : d0/d1 = (row g, cols 2t,2t+1), d2/d3 = (row g+8, ...)
    #pragma unroll
    for (int s = 0; s < 3; s++)
        #pragma unroll
        for (int f = 0; f < 2; f++) {
            const int c = f * 8 + 2 * t;
            *reinterpret_cast<float2*>(&g_U[s][kb][rlo][c]) =
                make_float2(D[s][f][0], D[s][f][1]);
            *reinterpret_cast<float2*>(&g_U[s][kb][rhi][c]) =
                make_float2(D[s][f][2], D[s][f][3]);
        }
}

__global__ __launch_bounds__(256) void mgsc_reduce(float* __restrict__ out)
{
    // thread per (n, c): 131072 threads -> 512 blocks (high occupancy)
    const int idx = blockIdx.x * 256 + threadIdx.x;
    const int n = idx >> 4;
    const int c = idx & 15;

    const float w[3] = {0.3f, 0.3f, 0.4f};
    float acc = 0.f;
    #pragma unroll
    for (int s = 0; s < 3; s++) {
        float u = 0.f, sm = 0.f;
        #pragma unroll
        for (int k = 0; k < KB_SPLIT; k++) {
            u  += g_U[s][k][n][c];
            sm += g_S[s][k][n];
        }
        acc += w[s] * u / sm;
    }
    out[idx] = acc;
}

extern "C" void kernel_launch(void* const* d_in, const int* in_sizes, int n_in,
                              void* d_out, int out_size)
{
    const float* x    = (const float*)d_in[0];
    const float* y    = (const float*)d_in[1];
    const float* yfea = (const float*)d_in[2];
    float*       out  = (float*)d_out;

    dim3 grid(N_PTS / 128, KB_SPLIT);        // (64, 16) = 1024 CTAs
    mgsc_pass1<<<grid, THREADS>>>(x, y, yfea);
    mgsc_reduce<<<(N_PTS * 16) / 256, 256>>>(out);   // 512 blocks
}